// round 16
// baseline (speedup 1.0000x reference)
#include <cuda_runtime.h>
#include <cuda_bf16.h>
#include <math.h>
#include <stdint.h>

#define TT 4096
#define DD 768
#define EE 8
#define KX 2
#define HH 2048

typedef __nv_bfloat16 bf16;
typedef unsigned long long u64;
typedef unsigned int u32;

// ---------------- fp32 scratch ----------------
__device__ __align__(16) float g_gateup[(size_t)2*EE*TT*HH];
__device__ __align__(16) float g_eo  [(size_t)TT*EE*DD];
__device__ __align__(16) float g_qkv [(size_t)TT*EE*3*DD];
__device__ __align__(16) float g_proj[(size_t)TT*EE*DD];
__device__ __align__(16) float g_ctx [(size_t)TT*EE*DD];
__device__ float g_rprobs[TT*EE];
__device__ int   g_tkidx[TT*KX];
__device__ float g_tkp  [TT*KX];
__device__ __align__(16) float g_sf [(size_t)TT*KX*DD];
__device__ __align__(16) float g_ao [(size_t)TT*KX*DD];
__device__ __align__(16) float g_h1 [(size_t)TT*KX*DD];
__device__ __align__(16) float g_ref[(size_t)TT*KX*DD];
__device__ float g_ent[TT];

// ---------------- bf16 split buffers (2 planes) ----------------
__device__ __align__(16) bf16 g_xS   [2*(size_t)TT*DD];
__device__ __align__(16) bf16 g_w13T [4*(size_t)EE*HH*DD];
__device__ __align__(16) bf16 g_w2T  [2*(size_t)EE*DD*HH];
__device__ __align__(16) bf16 g_actS [2*(size_t)EE*TT*HH];
__device__ __align__(16) bf16 g_eoS  [2*(size_t)TT*EE*DD];
__device__ __align__(16) bf16 g_gS   [2*(size_t)TT*EE*DD];
__device__ __align__(16) bf16 g_rinS [2*(size_t)3*DD*DD];
__device__ __align__(16) bf16 g_routS[2*(size_t)DD*DD];
__device__ __align__(16) bf16 g_cinS [2*(size_t)3*DD*DD];
__device__ __align__(16) bf16 g_coutS[2*(size_t)DD*DD];
__device__ __align__(16) bf16 g_f1S  [2*(size_t)DD*DD];
__device__ __align__(16) bf16 g_f2S  [2*(size_t)DD*DD];
__device__ __align__(16) bf16 g_owS  [2*(size_t)DD*DD];

// ---------------- PTX helpers (sm_80+ only) ----------------
__device__ __forceinline__ u32 s2u(const void* p) {
    u32 a; asm("{ .reg .u64 t; cvta.to.shared.u64 t, %1; cvt.u32.u64 %0, t; }" : "=r"(a) : "l"(p));
    return a;
}
__device__ __forceinline__ void cpasync16(u32 saddr, const void* gaddr) {
    asm volatile("cp.async.cg.shared.global [%0], [%1], 16;" :: "r"(saddr), "l"(gaddr));
}
#define CP_COMMIT() asm volatile("cp.async.commit_group;" ::: "memory")
#define CP_WAIT(n)  asm volatile("cp.async.wait_group %0;" :: "n"(n) : "memory")

__device__ __forceinline__ void ldmx4(u32* r, u32 addr) {
    asm volatile("ldmatrix.sync.aligned.m8n8.x4.shared.b16 {%0,%1,%2,%3}, [%4];"
        : "=r"(r[0]), "=r"(r[1]), "=r"(r[2]), "=r"(r[3]) : "r"(addr));
}
__device__ __forceinline__ void mma16816(float* d, const u32* a, const u32* b) {
    asm volatile("mma.sync.aligned.m16n8k16.row.col.f32.bf16.bf16.f32 "
        "{%0,%1,%2,%3}, {%4,%5,%6,%7}, {%8,%9}, {%0,%1,%2,%3};"
        : "+f"(d[0]), "+f"(d[1]), "+f"(d[2]), "+f"(d[3])
        : "r"(a[0]), "r"(a[1]), "r"(a[2]), "r"(a[3]), "r"(b[0]), "r"(b[1]));
}

// ---------------- exact 2-way bf16 split ----------------
__device__ __forceinline__ void split2(float x, bf16& h, bf16& m) {
    h = __float2bfloat16(x);
    m = __float2bfloat16(x - __bfloat162float(h));
}
__device__ __forceinline__ void split4_store(float4 v, bf16* ph, bf16* pm) {
    bf16 h0,m0,h1,m1,h2,m2,h3,m3;
    split2(v.x,h0,m0); split2(v.y,h1,m1); split2(v.z,h2,m2); split2(v.w,h3,m3);
    union { bf16 b[4]; uint2 u; } H, M;
    H.b[0]=h0; H.b[1]=h1; H.b[2]=h2; H.b[3]=h3;
    M.b[0]=m0; M.b[1]=m1; M.b[2]=m2; M.b[3]=m3;
    *(uint2*)ph = H.u;
    *(uint2*)pm = M.u;
}

__global__ void split3(const float* __restrict__ in, bf16* __restrict__ out,
                       size_t ss, size_t n4) {
    for (size_t i = (size_t)blockIdx.x*blockDim.x + threadIdx.x; i < n4;
         i += (size_t)gridDim.x*blockDim.x) {
        float4 v = ((const float4*)in)[i];
        split4_store(v, out + 4*i, out + ss + 4*i);
    }
}
__global__ void split3_swiglu(const float* __restrict__ g, const float* __restrict__ u,
                              bf16* __restrict__ out, size_t ss, size_t n4) {
    for (size_t i = (size_t)blockIdx.x*blockDim.x + threadIdx.x; i < n4;
         i += (size_t)gridDim.x*blockDim.x) {
        float4 gv = ((const float4*)g)[i];
        float4 uv = ((const float4*)u)[i];
        float4 a;
        a.x = gv.x / (1.0f + expf(-gv.x)) * uv.x;
        a.y = gv.y / (1.0f + expf(-gv.y)) * uv.y;
        a.z = gv.z / (1.0f + expf(-gv.z)) * uv.z;
        a.w = gv.w / (1.0f + expf(-gv.w)) * uv.w;
        split4_store(a, out + 4*i, out + ss + 4*i);
    }
}
__global__ void tsplit(const float* __restrict__ in, bf16* __restrict__ out,
                       int Kd, int Nd, size_t ss) {
    __shared__ float t[32][33];
    const float* ip = in + (size_t)blockIdx.z * Kd * Nd;
    bf16* op = out + (size_t)blockIdx.z * Kd * Nd;
    int n0 = blockIdx.x * 32, k0 = blockIdx.y * 32;
    int tx = threadIdx.x, ty0 = threadIdx.y;
    for (int ty = ty0; ty < 32; ty += 8)
        t[ty][tx] = ip[(size_t)(k0 + ty) * Nd + n0 + tx];
    __syncthreads();
    for (int ty = ty0; ty < 32; ty += 8) {
        bf16 h, m; split2(t[tx][ty], h, m);
        size_t o = (size_t)(n0 + ty) * Kd + k0 + tx;
        op[o] = h; op[ss + o] = m;
    }
}

// ================= WIDE GEMM: 128x256 tile, 512 threads, 2-stage ===========
#define A_TILE   18432
#define B_TILE   36864
#define B_OFF    (2*A_TILE)
#define STAGE_W  (2*A_TILE + 2*B_TILE)
#define SMEM_W   (2*STAGE_W)

__global__ void __launch_bounds__(512, 1) tgemmW(
    const bf16* __restrict__ A, size_t aSS, size_t sA,
    const bf16* __restrict__ B, size_t bSS, size_t sB,
    int Kd,
    const float* __restrict__ bias, const float* __restrict__ resid,
    float* __restrict__ C, int ldc, size_t sC, int epi)
{
    extern __shared__ __align__(16) char smc[];
    const int tid = threadIdx.x, wid = tid >> 5, lane = tid & 31;
    const u32 sb = s2u(smc);
    const int rowBase = blockIdx.y << 7;
    const int colBase = blockIdx.x << 8;
    const bf16* Az = A + (size_t)blockIdx.z * sA;
    const bf16* Bz = B + (size_t)blockIdx.z * sB;
    C += (size_t)blockIdx.z * sC;

    const int warpM = wid >> 2;
    const int warpN = wid & 3;

    auto loadChunk = [&](int c, int st) {
        const int k0 = c << 6;
        const u32 stBase = sb + (u32)st * STAGE_W;
        #pragma unroll
        for (int it = 0; it < 12; it++) {
            int idx = tid + (it << 9);
            if (idx < 2048) {
                int split = idx >> 10;
                int rc    = idx & 1023;
                int row   = rc >> 3;
                int seg   = rc & 7;
                const bf16* src = Az + (size_t)split * aSS
                    + (size_t)(rowBase + row) * Kd + k0 + (seg << 3);
                cpasync16(stBase + (u32)split * A_TILE + (u32)(row * 144 + (seg << 4)), src);
            } else {
                int i2    = idx - 2048;
                int split = i2 >> 11;
                int rc    = i2 & 2047;
                int row   = rc >> 3;
                int seg   = rc & 7;
                const bf16* src = Bz + (size_t)split * bSS
                    + (size_t)(colBase + row) * Kd + k0 + (seg << 3);
                cpasync16(stBase + B_OFF + (u32)split * B_TILE + (u32)(row * 144 + (seg << 4)), src);
            }
        }
    };

    float acc[2][8][4];
    #pragma unroll
    for (int mt = 0; mt < 2; mt++)
        #pragma unroll
        for (int nt = 0; nt < 8; nt++)
            #pragma unroll
            for (int j = 0; j < 4; j++) acc[mt][nt][j] = 0.f;

    const int nc = Kd >> 6;
    loadChunk(0, 0); CP_COMMIT();

    const int aRow = (warpM << 5) + (lane & 15);
    const u32 aColB = (u32)((lane >> 4) << 4);
    const int bRow = (warpN << 6) + ((lane >> 4) << 3) + (lane & 7);
    const u32 bColB = (u32)(((lane >> 3) & 1) << 4);

    for (int c = 0; c < nc; c++) {
        const int st = c & 1;
        if (c + 1 < nc) { loadChunk(c + 1, st ^ 1); CP_COMMIT(); CP_WAIT(1); }
        else CP_WAIT(0);
        __syncthreads();

        const u32 stBase = sb + (u32)st * STAGE_W;
        #pragma unroll
        for (int ks = 0; ks < 4; ks++) {
            const u32 kb = (u32)(ks << 5);
            u32 af[2][2][4];
            #pragma unroll
            for (int s = 0; s < 2; s++) {
                const u32 abase = stBase + (u32)s * A_TILE + kb + aColB;
                #pragma unroll
                for (int mt = 0; mt < 2; mt++)
                    ldmx4(af[s][mt], abase + (u32)((aRow + (mt << 4)) * 144));
            }
            u32 bf[8][2];
            {
                const u32 bbase = stBase + B_OFF + kb + bColB;
                #pragma unroll
                for (int p = 0; p < 4; p++) {
                    u32 t4[4];
                    ldmx4(t4, bbase + (u32)((bRow + (p << 4)) * 144));
                    bf[2*p][0] = t4[0]; bf[2*p][1] = t4[1];
                    bf[2*p+1][0] = t4[2]; bf[2*p+1][1] = t4[3];
                }
                #pragma unroll
                for (int s = 0; s < 2; s++)
                    #pragma unroll
                    for (int mt = 0; mt < 2; mt++)
                        #pragma unroll
                        for (int nt = 0; nt < 8; nt++)
                            mma16816(acc[mt][nt], af[s][mt], bf[nt]);
            }
            {
                const u32 bbase = stBase + B_OFF + (u32)B_TILE + kb + bColB;
                #pragma unroll
                for (int p = 0; p < 4; p++) {
                    u32 t4[4];
                    ldmx4(t4, bbase + (u32)((bRow + (p << 4)) * 144));
                    bf[2*p][0] = t4[0]; bf[2*p][1] = t4[1];
                    bf[2*p+1][0] = t4[2]; bf[2*p+1][1] = t4[3];
                }
                #pragma unroll
                for (int mt = 0; mt < 2; mt++)
                    #pragma unroll
                    for (int nt = 0; nt < 8; nt++)
                        mma16816(acc[mt][nt], af[0][mt], bf[nt]);
            }
        }
        __syncthreads();
    }

    const int qr = lane >> 2;
    const int qc = (lane & 3) << 1;
    #pragma unroll
    for (int mt = 0; mt < 2; mt++) {
        #pragma unroll
        for (int half = 0; half < 2; half++) {
            const int r = rowBase + (warpM << 5) + (mt << 4) + (half << 3) + qr;
            #pragma unroll
            for (int nt = 0; nt < 8; nt++) {
                const int cc = colBase + (warpN << 6) + (nt << 3) + qc;
                float v0 = acc[mt][nt][2*half + 0];
                float v1 = acc[mt][nt][2*half + 1];
                if (bias) { v0 += __ldg(&bias[cc]); v1 += __ldg(&bias[cc + 1]); }
                if (epi == 1) {
                    v0 = 0.5f * v0 * (1.0f + erff(v0 * 0.7071067811865475f));
                    v1 = 0.5f * v1 * (1.0f + erff(v1 * 0.7071067811865475f));
                }
                if (resid) {
                    v0 += resid[(size_t)r * ldc + cc];
                    v1 += resid[(size_t)r * ldc + cc + 1];
                }
                *(float2*)(C + (size_t)r * ldc + cc) = make_float2(v0, v1);
            }
        }
    }
}

// ================= NARROW GEMM: 128x128 tile, 256 threads, 3-stage =========
#define TILE_N   18432
#define STAGE_N  (4*TILE_N)
#define SMEM_N   (3*STAGE_N)      // 221184 (3 stages)

__global__ void __launch_bounds__(256, 1) tgemmN(
    const bf16* __restrict__ A, size_t aSS, size_t sA,
    const bf16* __restrict__ B, size_t bSS, size_t sB,
    int Kd,
    const float* __restrict__ bias, const float* __restrict__ resid,
    float* __restrict__ C, int ldc, size_t sC, int epi)
{
    extern __shared__ __align__(16) char smc[];
    const int tid = threadIdx.x, wid = tid >> 5, lane = tid & 31;
    const u32 sb = s2u(smc);
    const int rowBase = blockIdx.y << 7;
    const int colBase = blockIdx.x << 7;
    const bf16* Az = A + (size_t)blockIdx.z * sA;
    const bf16* Bz = B + (size_t)blockIdx.z * sB;
    C += (size_t)blockIdx.z * sC;

    const int warpM = wid >> 1;
    const int warpN = wid & 1;

    auto loadChunk = [&](int c, int st) {
        const int k0 = c << 6;
        const u32 stBase = sb + (u32)st * STAGE_N;
        #pragma unroll
        for (int it = 0; it < 16; it++) {
            int idx = tid + (it << 8);
            int mat   = idx >> 11;
            int split = (idx >> 10) & 1;
            int rc    = idx & 1023;
            int row   = rc >> 3;
            int seg   = rc & 7;
            const bf16* src = (mat == 0)
                ? Az + (size_t)split * aSS + (size_t)(rowBase + row) * Kd + k0 + (seg << 3)
                : Bz + (size_t)split * bSS + (size_t)(colBase + row) * Kd + k0 + (seg << 3);
            cpasync16(stBase + (u32)((mat << 1) + split) * TILE_N + (u32)(row * 144 + (seg << 4)), src);
        }
    };

    float acc[2][8][4];
    #pragma unroll
    for (int mt = 0; mt < 2; mt++)
        #pragma unroll
        for (int nt = 0; nt < 8; nt++)
            #pragma unroll
            for (int j = 0; j < 4; j++) acc[mt][nt][j] = 0.f;

    const int nc = Kd >> 6;   // 12 for Kd=768
    // prefetch 2 chunks
    loadChunk(0, 0); CP_COMMIT();
    if (nc > 1) { loadChunk(1, 1); CP_COMMIT(); }

    const int aRow = (warpM << 5) + (lane & 15);
    const u32 aColB = (u32)((lane >> 4) << 4);
    const int bRow = (warpN << 6) + ((lane >> 4) << 3) + (lane & 7);
    const u32 bColB = (u32)(((lane >> 3) & 1) << 4);

    int stCur = 0;
    for (int c = 0; c < nc; c++) {
        if (c + 2 < nc) {
            int st2 = (c + 2) % 3;
            loadChunk(c + 2, st2); CP_COMMIT();
            CP_WAIT(2);
        } else if (c + 1 < nc) {
            CP_WAIT(1);
        } else {
            CP_WAIT(0);
        }
        __syncthreads();

        const u32 stBase = sb + (u32)stCur * STAGE_N;
        #pragma unroll
        for (int ks = 0; ks < 4; ks++) {
            const u32 kb = (u32)(ks << 5);
            u32 af[2][2][4];
            #pragma unroll
            for (int s = 0; s < 2; s++) {
                const u32 abase = stBase + (u32)s * TILE_N + kb + aColB;
                #pragma unroll
                for (int mt = 0; mt < 2; mt++)
                    ldmx4(af[s][mt], abase + (u32)((aRow + (mt << 4)) * 144));
            }
            u32 bf[8][2];
            {
                const u32 bbase = stBase + (u32)2 * TILE_N + kb + bColB;
                #pragma unroll
                for (int p = 0; p < 4; p++) {
                    u32 t4[4];
                    ldmx4(t4, bbase + (u32)((bRow + (p << 4)) * 144));
                    bf[2*p][0] = t4[0]; bf[2*p][1] = t4[1];
                    bf[2*p+1][0] = t4[2]; bf[2*p+1][1] = t4[3];
                }
                #pragma unroll
                for (int s = 0; s < 2; s++)
                    #pragma unroll
                    for (int mt = 0; mt < 2; mt++)
                        #pragma unroll
                        for (int nt = 0; nt < 8; nt++)
                            mma16816(acc[mt][nt], af[s][mt], bf[nt]);
            }
            {
                const u32 bbase = stBase + (u32)3 * TILE_N + kb + bColB;
                #pragma unroll
                for (int p = 0; p < 4; p++) {
                    u32 t4[4];
                    ldmx4(t4, bbase + (u32)((bRow + (p << 4)) * 144));
                    bf[2*p][0] = t4[0]; bf[2*p][1] = t4[1];
                    bf[2*p+1][0] = t4[2]; bf[2*p+1][1] = t4[3];
                }
                #pragma unroll
                for (int mt = 0; mt < 2; mt++)
                    #pragma unroll
                    for (int nt = 0; nt < 8; nt++)
                        mma16816(acc[mt][nt], af[0][mt], bf[nt]);
            }
        }
        __syncthreads();
        stCur = (stCur + 1) % 3;
    }

    const int qr = lane >> 2;
    const int qc = (lane & 3) << 1;
    #pragma unroll
    for (int mt = 0; mt < 2; mt++) {
        #pragma unroll
        for (int half = 0; half < 2; half++) {
            const int r = rowBase + (warpM << 5) + (mt << 4) + (half << 3) + qr;
            #pragma unroll
            for (int nt = 0; nt < 8; nt++) {
                const int cc = colBase + (warpN << 6) + (nt << 3) + qc;
                float v0 = acc[mt][nt][2*half + 0];
                float v1 = acc[mt][nt][2*half + 1];
                if (bias) { v0 += __ldg(&bias[cc]); v1 += __ldg(&bias[cc + 1]); }
                if (epi == 1) {
                    v0 = 0.5f * v0 * (1.0f + erff(v0 * 0.7071067811865475f));
                    v1 = 0.5f * v1 * (1.0f + erff(v1 * 0.7071067811865475f));
                }
                if (resid) {
                    v0 += resid[(size_t)r * ldc + cc];
                    v1 += resid[(size_t)r * ldc + cc + 1];
                }
                *(float2*)(C + (size_t)r * ldc + cc) = make_float2(v0, v1);
            }
        }
    }
}

// ---------------- router self-attention -> bf16 split output ----------------
__global__ void __launch_bounds__(128) router_attn_kernel(
    const float* __restrict__ QKV, bf16* __restrict__ Os, size_t ss)
{
    __shared__ float sK[8 * 768];
    __shared__ float sV[8 * 768];
    const int t = blockIdx.x, tid = threadIdx.x;
    const float* base = QKV + (size_t)t * 8 * 2304;
    #pragma unroll
    for (int it = 0; it < 12; it++) {
        int i = tid + (it << 7);
        int pos = i / 192, c4 = i - pos * 192;
        ((float4*)sK)[i] = *(const float4*)(base + (size_t)pos * 2304 +  768 + c4 * 4);
        ((float4*)sV)[i] = *(const float4*)(base + (size_t)pos * 2304 + 1536 + c4 * 4);
    }
    __syncthreads();
    if (tid < 96) {
        const int head = tid / 8, qi = tid % 8;
        const float* q = base + (size_t)qi * 2304 + head * 64;
        float s[8] = {0.f};
        for (int d = 0; d < 64; d++) {
            float qd = q[d];
            #pragma unroll
            for (int m = 0; m < 8; m++) s[m] = fmaf(qd, sK[m * 768 + head * 64 + d], s[m]);
        }
        float mx = -1e30f;
        #pragma unroll
        for (int m = 0; m < 8; m++) { s[m] *= 0.125f; mx = fmaxf(mx, s[m]); }
        float den = 0.f;
        #pragma unroll
        for (int m = 0; m < 8; m++) { s[m] = expf(s[m] - mx); den += s[m]; }
        float inv = 1.0f / den;
        #pragma unroll
        for (int m = 0; m < 8; m++) s[m] *= inv;
        bf16* op = Os + (size_t)(t * 8 + qi) * 768 + head * 64;
        for (int d4 = 0; d4 < 16; d4++) {
            float4 o4;
            float* po = &o4.x;
            #pragma unroll
            for (int j = 0; j < 4; j++) {
                int d = d4 * 4 + j;
                float o = 0.f;
                #pragma unroll
                for (int m = 0; m < 8; m++) o = fmaf(s[m], sV[m * 768 + head * 64 + d], o);
                po[j] = o;
            }
            split4_store(o4, op + d4 * 4, op + ss + d4 * 4);
        }
    }
}

// ---------------- RMS-norm with residual; fp32 + optional split out ----------------
__global__ void __launch_bounds__(256) rms_kernel(
    const float* __restrict__ Y, const float* __restrict__ R,
    const float* __restrict__ W, float* __restrict__ O,
    bf16* __restrict__ Os, size_t oss)
{
    const int row = blockIdx.x, tid = threadIdx.x;
    float4 sv;
    float ssum = 0.f;
    if (tid < 192) {
        float4 vy = *(const float4*)(Y + (size_t)row * 768 + tid * 4);
        float4 vr = *(const float4*)(R + (size_t)row * 768 + tid * 4);
        sv.x = vy.x + vr.x; sv.y = vy.y + vr.y;
        sv.z = vy.z + vr.z; sv.w = vy.w + vr.w;
        ssum = sv.x*sv.x + sv.y*sv.y + sv.z*sv.z + sv.w*sv.w;
    }
    __shared__ float red[256];
    red[tid] = ssum; __syncthreads();
    for (int o = 128; o > 0; o >>= 1) { if (tid < o) red[tid] += red[tid + o]; __syncthreads(); }
    float scale = rsqrtf(red[0] * (1.0f / 768.0f) + 1e-5f);
    if (tid < 192) {
        float4 w = *(const float4*)(W + tid * 4);
        float4 o;
        o.x = sv.x * scale * w.x; o.y = sv.y * scale * w.y;
        o.z = sv.z * scale * w.z; o.w = sv.w * scale * w.w;
        size_t off = (size_t)row * 768 + tid * 4;
        *(float4*)(O + off) = o;
        if (Os) split4_store(o, Os + off, Os + oss + off);
    }
}

__global__ void __launch_bounds__(256) logits_kernel(
    const float* __restrict__ CTX, const float* __restrict__ GW,
    float* __restrict__ rprobs, int* __restrict__ tkidx,
    float* __restrict__ tkp, float* __restrict__ out_idx_f)
{
    const int t = blockIdx.x, tid = threadIdx.x;
    __shared__ float mv[768];
    const float* c0 = CTX + (size_t)t * 8 * 768;
    for (int i = tid; i < 768; i += 256) {
        float s = 0.f;
        #pragma unroll
        for (int p = 0; p < 8; p++) s += c0[p * 768 + i];
        mv[i] = s * 0.125f;
    }
    __syncthreads();
    const int w = tid >> 5, lane = tid & 31;
    float part = 0.f;
    for (int i = lane; i < 768; i += 32) part = fmaf(mv[i], GW[w * 768 + i], part);
    #pragma unroll
    for (int o = 16; o; o >>= 1) part += __shfl_xor_sync(0xffffffffu, part, o);
    __shared__ float lg[8];
    if (lane == 0) lg[w] = part;
    __syncthreads();
    if (tid == 0) {
        float mx = lg[0];
        #pragma unroll
        for (int e = 1; e < 8; e++) mx = fmaxf(mx, lg[e]);
        float ex[8], den = 0.f;
        #pragma unroll
        for (int e = 0; e < 8; e++) { ex[e] = expf(lg[e] - mx); den += ex[e]; }
        float inv = 1.0f / den;
        #pragma unroll
        for (int e = 0; e < 8; e++) rprobs[t * 8 + e] = ex[e] * inv;
        int i0 = 0;
        #pragma unroll
        for (int e = 1; e < 8; e++) if (lg[e] > lg[i0]) i0 = e;
        int i1 = -1;
        #pragma unroll
        for (int e = 0; e < 8; e++) if (e != i0 && (i1 < 0 || lg[e] > lg[i1])) i1 = e;
        tkidx[t * 2] = i0; tkidx[t * 2 + 1] = i1;
        float eb = expf(lg[i1] - lg[i0]);
        float p0 = 1.0f / (1.0f + eb);
        tkp[t * 2] = p0; tkp[t * 2 + 1] = eb * p0;
        if (out_idx_f) { out_idx_f[t * 2] = (float)i0; out_idx_f[t * 2 + 1] = (float)i1; }
    }
}

// ---------------- gather: fp32 + split output ----------------
__global__ void gather_kernel(const float* __restrict__ eo, const int* __restrict__ tkidx,
                              float* __restrict__ sf, bf16* __restrict__ sfS, size_t ss)
{
    const int total4 = TT * KX * DD / 4;
    for (int idx = blockIdx.x * blockDim.x + threadIdx.x; idx < total4; idx += gridDim.x * blockDim.x) {
        int d4 = idx % (DD / 4);
        int r = idx / (DD / 4);
        int t = r >> 1, k = r & 1;
        float4 v = *(const float4*)(eo + (size_t)t * EE * DD
                                    + (size_t)tkidx[t * 2 + k] * DD + d4 * 4);
        ((float4*)sf)[idx] = v;
        split4_store(v, sfS + 4 * (size_t)idx, sfS + ss + 4 * (size_t)idx);
    }
}

// ---------------- collab attention + entropy -> split output ----------------
__global__ void __launch_bounds__(256) collab_attn_kernel(
    const float* __restrict__ QKV, bf16* __restrict__ Os, size_t ss,
    float* __restrict__ ent)
{
    const int t = blockIdx.x, tid = threadIdx.x;
    const float* base = QKV + (size_t)t * 2 * 2304;
    __shared__ float sc[2][2][2];
    __shared__ float sp[2][2][2];
    const int w = tid >> 5, lane = tid & 31;
    {
        int h = (w >> 2) & 1, qi = (w >> 1) & 1, kj = w & 1;
        float part = 0.f;
        const float* qp = base + (size_t)qi * 2304 + h * 384;
        const float* kp = base + (size_t)kj * 2304 + 768 + h * 384;
        for (int d = lane; d < 384; d += 32) part = fmaf(qp[d], kp[d], part);
        #pragma unroll
        for (int o = 16; o; o >>= 1) part += __shfl_xor_sync(0xffffffffu, part, o);
        if (lane == 0) sc[h][qi][kj] = part * 0.05103103630798288f;
    }
    __syncthreads();
    if (tid < 4) {
        int h = tid >> 1, qi = tid & 1;
        float s0 = sc[h][qi][0], s1 = sc[h][qi][1];
        float m = fmaxf(s0, s1);
        float e0 = expf(s0 - m), e1 = expf(s1 - m);
        float inv = 1.0f / (e0 + e1);
        sp[h][qi][0] = e0 * inv; sp[h][qi][1] = e1 * inv;
    }
    __syncthreads();
    if (tid == 0) {
        float esum = 0.f;
        #pragma unroll
        for (int qi = 0; qi < 2; qi++) {
            float a0 = 0.5f * (sp[0][qi][0] + sp[1][qi][0]);
            float a1 = 0.5f * (sp[0][qi][1] + sp[1][qi][1]);
            esum -= a0 * logf(a0 + 1e-9f) + a1 * logf(a1 + 1e-9f);
        }
        ent[t] = esum;
    }
    for (int i4 = tid; i4 < 384; i4 += 256) {
        int qi = i4 / 192, c4 = i4 - qi * 192;
        int c = c4 * 4;
        int h = c / 384;
        float p0 = sp[h][qi][0], p1 = sp[h][qi][1];
        float4 v0 = *(const float4*)(base + 1536 + c);
        float4 v1 = *(const float4*)(base + 2304 + 1536 + c);
        float4 o;
        o.x = fmaf(p0, v0.x, p1 * v1.x); o.y = fmaf(p0, v0.y, p1 * v1.y);
        o.z = fmaf(p0, v0.z, p1 * v1.z); o.w = fmaf(p0, v0.w, p1 * v1.w);
        size_t off = (size_t)(t * 2 + qi) * 768 + c;
        split4_store(o, Os + off, Os + ss + off);
    }
}

// ---------------- weighted combine -> split output only ----------------
__global__ void combine_kernel(const float* __restrict__ ref, const float* __restrict__ tkp,
                               bf16* __restrict__ outS, size_t ss)
{
    const int total4 = TT * DD / 4;
    for (int idx = blockIdx.x * blockDim.x + threadIdx.x; idx < total4; idx += gridDim.x * blockDim.x) {
        int d4 = idx % (DD / 4);
        int t = idx / (DD / 4);
        float p0 = tkp[t * 2], p1 = tkp[t * 2 + 1];
        float4 a = *(const float4*)(ref + (size_t)(t * 2) * DD + d4 * 4);
        float4 b = *(const float4*)(ref + (size_t)(t * 2 + 1) * DD + d4 * 4);
        float4 o;
        o.x = fmaf(p0, a.x, p1 * b.x); o.y = fmaf(p0, a.y, p1 * b.y);
        o.z = fmaf(p0, a.z, p1 * b.z); o.w = fmaf(p0, a.w, p1 * b.w);
        split4_store(o, outS + 4 * (size_t)idx, outS + ss + 4 * (size_t)idx);
    }
}

__global__ void __launch_bounds__(256) aux_kernel(
    const float* __restrict__ rprobs, const float* __restrict__ ent, float* __restrict__ outp)
{
    const int tid = threadIdx.x;
    __shared__ float red[256];
    float us[8] = {0.f};
    for (int t = tid; t < TT; t += 256)
        #pragma unroll
        for (int e = 0; e < 8; e++) us[e] += rprobs[t * 8 + e];
    float usage[8];
    for (int e = 0; e < 8; e++) {
        red[tid] = us[e]; __syncthreads();
        for (int o = 128; o > 0; o >>= 1) { if (tid < o) red[tid] += red[tid + o]; __syncthreads(); }
        usage[e] = red[0] / (float)TT; __syncthreads();
    }
    float es = 0.f;
    for (int t = tid; t < TT; t += 256) es += ent[t];
    red[tid] = es; __syncthreads();
    for (int o = 128; o > 0; o >>= 1) { if (tid < o) red[tid] += red[tid + o]; __syncthreads(); }
    if (tid == 0) {
        float um = 0.f;
        #pragma unroll
        for (int e = 0; e < 8; e++) um += usage[e];
        um *= 0.125f;
        float bal = 0.f;
        #pragma unroll
        for (int e = 0; e < 8; e++) { float d = usage[e] - um; bal = fmaf(d, d, bal); }
        bal *= 0.125f;
        outp[0] = 0.1f * (0.01f * (red[0] / (float)(TT * KX)) + 0.01f * bal);
    }
}

// ---------------- host launch ----------------
extern "C" void kernel_launch(void* const* d_in, const int* in_sizes, int n_in,
                              void* d_out, int out_size)
{
    const float* x       = (const float*)d_in[0];
    const float* w1      = (const float*)d_in[1];
    const float* w3      = (const float*)d_in[2];
    const float* w2      = (const float*)d_in[3];
    const float* r_in_w  = (const float*)d_in[4];
    const float* r_in_b  = (const float*)d_in[5];
    const float* r_out_w = (const float*)d_in[6];
    const float* r_out_b = (const float*)d_in[7];
    const float* r_norm  = (const float*)d_in[8];
    const float* gate_w  = (const float*)d_in[9];
    const float* c_in_w  = (const float*)d_in[10];
    const float* c_in_b  = (const float*)d_in[11];
    const float* c_out_w = (const float*)d_in[12];
    const float* c_out_b = (const float*)d_in[13];
    const float* c_norm  = (const float*)d_in[14];
    const float* ffn_w1  = (const float*)d_in[15];
    const float* ffn_w2  = (const float*)d_in[16];
    const float* o_w     = (const float*)d_in[17];
    float* out = (float*)d_out;

    static cudaStream_t s2 = nullptr;
    static cudaEvent_t evFork = nullptr, evJoin = nullptr, evFork2 = nullptr, evJoin2 = nullptr;
    static bool attr_done = false;
    if (!attr_done) {
        cudaFuncSetAttribute(tgemmW, cudaFuncAttributeMaxDynamicSharedMemorySize, SMEM_W);
        cudaFuncSetAttribute(tgemmN, cudaFuncAttributeMaxDynamicSharedMemorySize, SMEM_N);
        cudaStreamCreateWithFlags(&s2, cudaStreamNonBlocking);
        cudaEventCreateWithFlags(&evFork,  cudaEventDisableTiming);
        cudaEventCreateWithFlags(&evJoin,  cudaEventDisableTiming);
        cudaEventCreateWithFlags(&evFork2, cudaEventDisableTiming);
        cudaEventCreateWithFlags(&evJoin2, cudaEventDisableTiming);
        attr_done = true;
    }

    float *gateup, *eo, *qkv, *proj, *ctx, *rprobs, *tkp, *sf, *ao, *h1, *ref, *ent;
    int* tkidx;
    bf16 *xS, *w13T, *w2T, *actS, *eoS, *gS, *rinS, *routS, *cinS, *coutS, *f1S, *f2S, *owS;
    cudaGetSymbolAddress((void**)&gateup, g_gateup);
    cudaGetSymbolAddress((void**)&eo,    g_eo);
    cudaGetSymbolAddress((void**)&qkv,   g_qkv);
    cudaGetSymbolAddress((void**)&proj,  g_proj);
    cudaGetSymbolAddress((void**)&ctx,   g_ctx);
    cudaGetSymbolAddress((void**)&rprobs,g_rprobs);
    cudaGetSymbolAddress((void**)&tkidx, g_tkidx);
    cudaGetSymbolAddress((void**)&tkp,   g_tkp);
    cudaGetSymbolAddress((void**)&sf,    g_sf);
    cudaGetSymbolAddress((void**)&ao,    g_ao);
    cudaGetSymbolAddress((void**)&h1,    g_h1);
    cudaGetSymbolAddress((void**)&ref,   g_ref);
    cudaGetSymbolAddress((void**)&ent,   g_ent);
    cudaGetSymbolAddress((void**)&xS,    g_xS);
    cudaGetSymbolAddress((void**)&w13T,  g_w13T);
    cudaGetSymbolAddress((void**)&w2T,   g_w2T);
    cudaGetSymbolAddress((void**)&actS,  g_actS);
    cudaGetSymbolAddress((void**)&eoS,   g_eoS);
    cudaGetSymbolAddress((void**)&gS,    g_gS);
    cudaGetSymbolAddress((void**)&rinS,  g_rinS);
    cudaGetSymbolAddress((void**)&routS, g_routS);
    cudaGetSymbolAddress((void**)&cinS,  g_cinS);
    cudaGetSymbolAddress((void**)&coutS, g_coutS);
    cudaGetSymbolAddress((void**)&f1S,   g_f1S);
    cudaGetSymbolAddress((void**)&f2S,   g_f2S);
    cudaGetSymbolAddress((void**)&owS,   g_owS);

    const bool write_idx = out_size >= (TT * DD + 1 + TT * KX);
    const bool write_aux = out_size >= (TT * DD + 1);
    const size_t sEHD = (size_t)EE * HH * DD;
    const size_t sETH = (size_t)EE * TT * HH;
    const size_t sBig = (size_t)TT * EE * DD;
    const size_t sMid = (size_t)TT * KX * DD;
    const size_t sSm  = (size_t)TT * DD;
    dim3 tb32(32, 8);

    // ---- fork: side stream weight prep concurrent with gate+up path ----
    cudaEventRecord(evFork, 0);
    cudaStreamWaitEvent(s2, evFork, 0);
    tsplit<<<dim3(DD/32, HH/32, EE), tb32, 0, s2>>>(w2, w2T, HH, DD, (size_t)EE * DD * HH);
    split3<<<512, 256, 0, s2>>>(r_in_w, rinS, (size_t)3*DD*DD, (size_t)3*DD*DD/4);
    split3<<<256, 256, 0, s2>>>(r_out_w, routS, (size_t)DD*DD, (size_t)DD*DD/4);
    split3<<<512, 256, 0, s2>>>(c_in_w, cinS, (size_t)3*DD*DD, (size_t)3*DD*DD/4);
    split3<<<256, 256, 0, s2>>>(c_out_w, coutS, (size_t)DD*DD, (size_t)DD*DD/4);
    split3<<<256, 256, 0, s2>>>(ffn_w1, f1S, (size_t)DD*DD, (size_t)DD*DD/4);
    split3<<<256, 256, 0, s2>>>(ffn_w2, f2S, (size_t)DD*DD, (size_t)DD*DD/4);
    split3<<<256, 256, 0, s2>>>(o_w, owS, (size_t)DD*DD, (size_t)DD*DD/4);
    cudaEventRecord(evJoin, s2);

    // main stream
    split3<<<512, 256>>>(x, xS, sSm, sSm / 4);
    tsplit<<<dim3(HH/32, DD/32, EE), tb32>>>(w1, w13T, DD, HH, 2*sEHD);
    tsplit<<<dim3(HH/32, DD/32, EE), tb32>>>(w3, w13T + sEHD, DD, HH, 2*sEHD);
    tgemmW<<<dim3(HH/256, TT/128, 16), 512, SMEM_W>>>(
        xS, sSm, 0, w13T, 2*sEHD, (size_t)HH*DD, DD,
        nullptr, nullptr, gateup, HH, (size_t)TT*HH, 0);
    split3_swiglu<<<4096, 256>>>(gateup, gateup + sETH, actS, sETH, sETH / 4);

    cudaStreamWaitEvent(0, evJoin, 0);

    // expert down-proj
    tgemmW<<<dim3(DD/256, TT/128, EE), 512, SMEM_W>>>(
        actS, sETH, (size_t)TT*HH, w2T, (size_t)EE*DD*HH, (size_t)DD*HH, HH,
        nullptr, nullptr, eo, EE*DD, (size_t)DD, 0);
    // router qkv
    split3<<<2048, 256>>>(eo, eoS, sBig, sBig / 4);
    tgemmW<<<dim3(3*DD/256, TT*EE/128, 1), 512, SMEM_W>>>(
        eoS, sBig, 0, rinS, (size_t)3*DD*DD, 0, DD,
        r_in_b, nullptr, qkv, 3*DD, 0, 0);
    // router attention -> gS splits (fused)
    router_attn_kernel<<<TT, 128>>>(qkv, gS, sBig);
    // router out-proj
    tgemmW<<<dim3(DD/256, TT*EE/128, 1), 512, SMEM_W>>>(
        gS, sBig, 0, routS, (size_t)DD*DD, 0, DD,
        r_out_b, nullptr, proj, DD, 0, 0);
    // residual + RMS -> ctx fp32
    rms_kernel<<<TT * EE, 256>>>(proj, eo, r_norm, ctx, nullptr, 0);
    // logits / top-2
    logits_kernel<<<TT, 256>>>(ctx, gate_w, rprobs, tkidx, tkp,
                               write_idx ? out + sSm + 1 : nullptr);
    // gather -> sf fp32 + gS splits (fused)
    gather_kernel<<<1024, 256>>>(eo, tkidx, sf, gS, sMid);
    // collab qkv
    tgemmN<<<dim3(3*DD/128, TT*KX/128, 1), 256, SMEM_N>>>(
        gS, sMid, 0, cinS, (size_t)3*DD*DD, 0, DD,
        c_in_b, nullptr, qkv, 3*DD, 0, 0);
    // collab attention + entropy -> gS splits (fused)
    collab_attn_kernel<<<TT, 256>>>(qkv, gS, sMid, ent);

    // ---- fork 2: aux loss on side stream ----
    if (write_aux) {
        cudaEventRecord(evFork2, 0);
        cudaStreamWaitEvent(s2, evFork2, 0);
        aux_kernel<<<1, 256, 0, s2>>>(rprobs, ent, out + sSm);
        cudaEventRecord(evJoin2, s2);
    }

    // collab out-proj
    tgemmN<<<dim3(DD/128, TT*KX/128, 1), 256, SMEM_N>>>(
        gS, sMid, 0, coutS, (size_t)DD*DD, 0, DD,
        c_out_b, nullptr, proj, DD, 0, 0);
    // residual + RMS -> ao fp32 + gS splits (fused)
    rms_kernel<<<TT * KX, 256>>>(proj, sf, c_norm, ao, gS, sMid);
    // FFN up + GELU
    tgemmN<<<dim3(DD/128, TT*KX/128, 1), 256, SMEM_N>>>(
        gS, sMid, 0, f1S, (size_t)DD*DD, 0, DD,
        nullptr, nullptr, h1, DD, 0, 1);
    // FFN down + residual(ao)
    split3<<<1024, 256>>>(h1, gS, sMid, sMid / 4);
    tgemmN<<<dim3(DD/128, TT*KX/128, 1), 256, SMEM_N>>>(
        gS, sMid, 0, f2S, (size_t)DD*DD, 0, DD,
        nullptr, ao, ref, DD, 0, 0);
    // combine -> gS splits (fused)
    combine_kernel<<<1024, 256>>>(ref, tkp, gS, sSm);
    // output projection
    tgemmN<<<dim3(DD/128, TT/128, 1), 256, SMEM_N>>>(
        gS, sSm, 0, owS, (size_t)DD*DD, 0, DD,
        nullptr, nullptr, out, DD, 0, 0);

    if (write_aux)
        cudaStreamWaitEvent(0, evJoin2, 0);
}

// round 17
// speedup vs baseline: 1.0079x; 1.0079x over previous
#include <cuda_runtime.h>
#include <cuda_bf16.h>
#include <math.h>
#include <stdint.h>

#define TT 4096
#define DD 768
#define EE 8
#define KX 2
#define HH 2048

typedef __nv_bfloat16 bf16;
typedef unsigned long long u64;
typedef unsigned int u32;

// ---------------- fp32 scratch ----------------
__device__ __align__(16) float g_gateup[(size_t)2*EE*TT*HH];
__device__ __align__(16) float g_eo  [(size_t)TT*EE*DD];
__device__ __align__(16) float g_qkv [(size_t)TT*EE*3*DD];
__device__ __align__(16) float g_proj[(size_t)TT*EE*DD];
__device__ __align__(16) float g_ctx [(size_t)TT*EE*DD];
__device__ float g_rprobs[TT*EE];
__device__ int   g_tkidx[TT*KX];
__device__ float g_tkp  [TT*KX];
__device__ __align__(16) float g_sf [(size_t)TT*KX*DD];
__device__ __align__(16) float g_ao [(size_t)TT*KX*DD];
__device__ __align__(16) float g_h1 [(size_t)TT*KX*DD];
__device__ __align__(16) float g_ref[(size_t)TT*KX*DD];
__device__ float g_ent[TT];

// ---------------- bf16 split buffers (2 planes) ----------------
__device__ __align__(16) bf16 g_xS   [2*(size_t)TT*DD];
__device__ __align__(16) bf16 g_w13T [4*(size_t)EE*HH*DD];
__device__ __align__(16) bf16 g_w2T  [2*(size_t)EE*DD*HH];
__device__ __align__(16) bf16 g_actS [2*(size_t)EE*TT*HH];
__device__ __align__(16) bf16 g_eoS  [2*(size_t)TT*EE*DD];
__device__ __align__(16) bf16 g_gS   [2*(size_t)TT*EE*DD];
__device__ __align__(16) bf16 g_rinS [2*(size_t)3*DD*DD];
__device__ __align__(16) bf16 g_routS[2*(size_t)DD*DD];
__device__ __align__(16) bf16 g_cinS [2*(size_t)3*DD*DD];
__device__ __align__(16) bf16 g_coutS[2*(size_t)DD*DD];
__device__ __align__(16) bf16 g_f1S  [2*(size_t)DD*DD];
__device__ __align__(16) bf16 g_f2S  [2*(size_t)DD*DD];
__device__ __align__(16) bf16 g_owS  [2*(size_t)DD*DD];

// ---------------- PTX helpers (sm_80+ only) ----------------
__device__ __forceinline__ u32 s2u(const void* p) {
    u32 a; asm("{ .reg .u64 t; cvta.to.shared.u64 t, %1; cvt.u32.u64 %0, t; }" : "=r"(a) : "l"(p));
    return a;
}
__device__ __forceinline__ void cpasync16(u32 saddr, const void* gaddr) {
    asm volatile("cp.async.cg.shared.global [%0], [%1], 16;" :: "r"(saddr), "l"(gaddr));
}
#define CP_COMMIT() asm volatile("cp.async.commit_group;" ::: "memory")
#define CP_WAIT(n)  asm volatile("cp.async.wait_group %0;" :: "n"(n) : "memory")

__device__ __forceinline__ void ldmx4(u32* r, u32 addr) {
    asm volatile("ldmatrix.sync.aligned.m8n8.x4.shared.b16 {%0,%1,%2,%3}, [%4];"
        : "=r"(r[0]), "=r"(r[1]), "=r"(r[2]), "=r"(r[3]) : "r"(addr));
}
__device__ __forceinline__ void mma16816(float* d, const u32* a, const u32* b) {
    asm volatile("mma.sync.aligned.m16n8k16.row.col.f32.bf16.bf16.f32 "
        "{%0,%1,%2,%3}, {%4,%5,%6,%7}, {%8,%9}, {%0,%1,%2,%3};"
        : "+f"(d[0]), "+f"(d[1]), "+f"(d[2]), "+f"(d[3])
        : "r"(a[0]), "r"(a[1]), "r"(a[2]), "r"(a[3]), "r"(b[0]), "r"(b[1]));
}

// ---------------- exact 2-way bf16 split ----------------
__device__ __forceinline__ void split2(float x, bf16& h, bf16& m) {
    h = __float2bfloat16(x);
    m = __float2bfloat16(x - __bfloat162float(h));
}
__device__ __forceinline__ void split4_store(float4 v, bf16* ph, bf16* pm) {
    bf16 h0,m0,h1,m1,h2,m2,h3,m3;
    split2(v.x,h0,m0); split2(v.y,h1,m1); split2(v.z,h2,m2); split2(v.w,h3,m3);
    union { bf16 b[4]; uint2 u; } H, M;
    H.b[0]=h0; H.b[1]=h1; H.b[2]=h2; H.b[3]=h3;
    M.b[0]=m0; M.b[1]=m1; M.b[2]=m2; M.b[3]=m3;
    *(uint2*)ph = H.u;
    *(uint2*)pm = M.u;
}

__global__ void split3(const float* __restrict__ in, bf16* __restrict__ out,
                       size_t ss, size_t n4) {
    for (size_t i = (size_t)blockIdx.x*blockDim.x + threadIdx.x; i < n4;
         i += (size_t)gridDim.x*blockDim.x) {
        float4 v = ((const float4*)in)[i];
        split4_store(v, out + 4*i, out + ss + 4*i);
    }
}
__global__ void split3_swiglu(const float* __restrict__ g, const float* __restrict__ u,
                              bf16* __restrict__ out, size_t ss, size_t n4) {
    for (size_t i = (size_t)blockIdx.x*blockDim.x + threadIdx.x; i < n4;
         i += (size_t)gridDim.x*blockDim.x) {
        float4 gv = ((const float4*)g)[i];
        float4 uv = ((const float4*)u)[i];
        float4 a;
        a.x = gv.x / (1.0f + expf(-gv.x)) * uv.x;
        a.y = gv.y / (1.0f + expf(-gv.y)) * uv.y;
        a.z = gv.z / (1.0f + expf(-gv.z)) * uv.z;
        a.w = gv.w / (1.0f + expf(-gv.w)) * uv.w;
        split4_store(a, out + 4*i, out + ss + 4*i);
    }
}
__global__ void tsplit(const float* __restrict__ in, bf16* __restrict__ out,
                       int Kd, int Nd, size_t ss) {
    __shared__ float t[32][33];
    const float* ip = in + (size_t)blockIdx.z * Kd * Nd;
    bf16* op = out + (size_t)blockIdx.z * Kd * Nd;
    int n0 = blockIdx.x * 32, k0 = blockIdx.y * 32;
    int tx = threadIdx.x, ty0 = threadIdx.y;
    for (int ty = ty0; ty < 32; ty += 8)
        t[ty][tx] = ip[(size_t)(k0 + ty) * Nd + n0 + tx];
    __syncthreads();
    for (int ty = ty0; ty < 32; ty += 8) {
        bf16 h, m; split2(t[tx][ty], h, m);
        size_t o = (size_t)(n0 + ty) * Kd + k0 + tx;
        op[o] = h; op[ss + o] = m;
    }
}

// ================= WIDE GEMM: 128x256 tile, 512 threads, 2-stage ===========
#define A_TILE   18432
#define B_TILE   36864
#define B_OFF    (2*A_TILE)
#define STAGE_W  (2*A_TILE + 2*B_TILE)
#define SMEM_W   (2*STAGE_W)

__global__ void __launch_bounds__(512, 1) tgemmW(
    const bf16* __restrict__ A, size_t aSS, size_t sA,
    const bf16* __restrict__ B, size_t bSS, size_t sB,
    int Kd,
    const float* __restrict__ bias, const float* __restrict__ resid,
    float* __restrict__ C, int ldc, size_t sC, int epi)
{
    extern __shared__ __align__(16) char smc[];
    const int tid = threadIdx.x, wid = tid >> 5, lane = tid & 31;
    const u32 sb = s2u(smc);
    const int rowBase = blockIdx.y << 7;
    const int colBase = blockIdx.x << 8;
    const bf16* Az = A + (size_t)blockIdx.z * sA;
    const bf16* Bz = B + (size_t)blockIdx.z * sB;
    C += (size_t)blockIdx.z * sC;

    const int warpM = wid >> 2;
    const int warpN = wid & 3;

    auto loadChunk = [&](int c, int st) {
        const int k0 = c << 6;
        const u32 stBase = sb + (u32)st * STAGE_W;
        #pragma unroll
        for (int it = 0; it < 12; it++) {
            int idx = tid + (it << 9);
            if (idx < 2048) {
                int split = idx >> 10;
                int rc    = idx & 1023;
                int row   = rc >> 3;
                int seg   = rc & 7;
                const bf16* src = Az + (size_t)split * aSS
                    + (size_t)(rowBase + row) * Kd + k0 + (seg << 3);
                cpasync16(stBase + (u32)split * A_TILE + (u32)(row * 144 + (seg << 4)), src);
            } else {
                int i2    = idx - 2048;
                int split = i2 >> 11;
                int rc    = i2 & 2047;
                int row   = rc >> 3;
                int seg   = rc & 7;
                const bf16* src = Bz + (size_t)split * bSS
                    + (size_t)(colBase + row) * Kd + k0 + (seg << 3);
                cpasync16(stBase + B_OFF + (u32)split * B_TILE + (u32)(row * 144 + (seg << 4)), src);
            }
        }
    };

    float acc[2][8][4];
    #pragma unroll
    for (int mt = 0; mt < 2; mt++)
        #pragma unroll
        for (int nt = 0; nt < 8; nt++)
            #pragma unroll
            for (int j = 0; j < 4; j++) acc[mt][nt][j] = 0.f;

    const int nc = Kd >> 6;
    loadChunk(0, 0); CP_COMMIT();

    const int aRow = (warpM << 5) + (lane & 15);
    const u32 aColB = (u32)((lane >> 4) << 4);
    const int bRow = (warpN << 6) + ((lane >> 4) << 3) + (lane & 7);
    const u32 bColB = (u32)(((lane >> 3) & 1) << 4);

    for (int c = 0; c < nc; c++) {
        const int st = c & 1;
        if (c + 1 < nc) { loadChunk(c + 1, st ^ 1); CP_COMMIT(); CP_WAIT(1); }
        else CP_WAIT(0);
        __syncthreads();

        const u32 stBase = sb + (u32)st * STAGE_W;
        #pragma unroll
        for (int ks = 0; ks < 4; ks++) {
            const u32 kb = (u32)(ks << 5);
            u32 af[2][2][4];
            #pragma unroll
            for (int s = 0; s < 2; s++) {
                const u32 abase = stBase + (u32)s * A_TILE + kb + aColB;
                #pragma unroll
                for (int mt = 0; mt < 2; mt++)
                    ldmx4(af[s][mt], abase + (u32)((aRow + (mt << 4)) * 144));
            }
            u32 bf[8][2];
            {
                const u32 bbase = stBase + B_OFF + kb + bColB;
                #pragma unroll
                for (int p = 0; p < 4; p++) {
                    u32 t4[4];
                    ldmx4(t4, bbase + (u32)((bRow + (p << 4)) * 144));
                    bf[2*p][0] = t4[0]; bf[2*p][1] = t4[1];
                    bf[2*p+1][0] = t4[2]; bf[2*p+1][1] = t4[3];
                }
                #pragma unroll
                for (int s = 0; s < 2; s++)
                    #pragma unroll
                    for (int mt = 0; mt < 2; mt++)
                        #pragma unroll
                        for (int nt = 0; nt < 8; nt++)
                            mma16816(acc[mt][nt], af[s][mt], bf[nt]);
            }
            {
                const u32 bbase = stBase + B_OFF + (u32)B_TILE + kb + bColB;
                #pragma unroll
                for (int p = 0; p < 4; p++) {
                    u32 t4[4];
                    ldmx4(t4, bbase + (u32)((bRow + (p << 4)) * 144));
                    bf[2*p][0] = t4[0]; bf[2*p][1] = t4[1];
                    bf[2*p+1][0] = t4[2]; bf[2*p+1][1] = t4[3];
                }
                #pragma unroll
                for (int mt = 0; mt < 2; mt++)
                    #pragma unroll
                    for (int nt = 0; nt < 8; nt++)
                        mma16816(acc[mt][nt], af[0][mt], bf[nt]);
            }
        }
        __syncthreads();
    }

    const int qr = lane >> 2;
    const int qc = (lane & 3) << 1;
    #pragma unroll
    for (int mt = 0; mt < 2; mt++) {
        #pragma unroll
        for (int half = 0; half < 2; half++) {
            const int r = rowBase + (warpM << 5) + (mt << 4) + (half << 3) + qr;
            #pragma unroll
            for (int nt = 0; nt < 8; nt++) {
                const int cc = colBase + (warpN << 6) + (nt << 3) + qc;
                float v0 = acc[mt][nt][2*half + 0];
                float v1 = acc[mt][nt][2*half + 1];
                if (bias) { v0 += __ldg(&bias[cc]); v1 += __ldg(&bias[cc + 1]); }
                if (epi == 1) {
                    v0 = 0.5f * v0 * (1.0f + erff(v0 * 0.7071067811865475f));
                    v1 = 0.5f * v1 * (1.0f + erff(v1 * 0.7071067811865475f));
                }
                if (resid) {
                    v0 += resid[(size_t)r * ldc + cc];
                    v1 += resid[(size_t)r * ldc + cc + 1];
                }
                *(float2*)(C + (size_t)r * ldc + cc) = make_float2(v0, v1);
            }
        }
    }
}

// ================= NARROW GEMM: 128x128 tile, 256 threads, 2-stage =========
#define TILE_N   18432
#define STAGE_N  (4*TILE_N)
#define SMEM_N   (2*STAGE_N)      // 147456

__global__ void __launch_bounds__(256, 1) tgemmN(
    const bf16* __restrict__ A, size_t aSS, size_t sA,
    const bf16* __restrict__ B, size_t bSS, size_t sB,
    int Kd,
    const float* __restrict__ bias, const float* __restrict__ resid,
    float* __restrict__ C, int ldc, size_t sC, int epi)
{
    extern __shared__ __align__(16) char smc[];
    const int tid = threadIdx.x, wid = tid >> 5, lane = tid & 31;
    const u32 sb = s2u(smc);
    const int rowBase = blockIdx.y << 7;
    const int colBase = blockIdx.x << 7;
    const bf16* Az = A + (size_t)blockIdx.z * sA;
    const bf16* Bz = B + (size_t)blockIdx.z * sB;
    C += (size_t)blockIdx.z * sC;

    const int warpM = wid >> 1;
    const int warpN = wid & 1;

    auto loadChunk = [&](int c, int st) {
        const int k0 = c << 6;
        const u32 stBase = sb + (u32)st * STAGE_N;
        #pragma unroll
        for (int it = 0; it < 16; it++) {
            int idx = tid + (it << 8);
            int mat   = idx >> 11;
            int split = (idx >> 10) & 1;
            int rc    = idx & 1023;
            int row   = rc >> 3;
            int seg   = rc & 7;
            const bf16* src = (mat == 0)
                ? Az + (size_t)split * aSS + (size_t)(rowBase + row) * Kd + k0 + (seg << 3)
                : Bz + (size_t)split * bSS + (size_t)(colBase + row) * Kd + k0 + (seg << 3);
            cpasync16(stBase + (u32)((mat << 1) + split) * TILE_N + (u32)(row * 144 + (seg << 4)), src);
        }
    };

    float acc[2][8][4];
    #pragma unroll
    for (int mt = 0; mt < 2; mt++)
        #pragma unroll
        for (int nt = 0; nt < 8; nt++)
            #pragma unroll
            for (int j = 0; j < 4; j++) acc[mt][nt][j] = 0.f;

    const int nc = Kd >> 6;
    loadChunk(0, 0); CP_COMMIT();

    const int aRow = (warpM << 5) + (lane & 15);
    const u32 aColB = (u32)((lane >> 4) << 4);
    const int bRow = (warpN << 6) + ((lane >> 4) << 3) + (lane & 7);
    const u32 bColB = (u32)(((lane >> 3) & 1) << 4);

    for (int c = 0; c < nc; c++) {
        const int st = c & 1;
        if (c + 1 < nc) { loadChunk(c + 1, st ^ 1); CP_COMMIT(); CP_WAIT(1); }
        else CP_WAIT(0);
        __syncthreads();

        const u32 stBase = sb + (u32)st * STAGE_N;
        #pragma unroll
        for (int ks = 0; ks < 4; ks++) {
            const u32 kb = (u32)(ks << 5);
            u32 af[2][2][4];
            #pragma unroll
            for (int s = 0; s < 2; s++) {
                const u32 abase = stBase + (u32)s * TILE_N + kb + aColB;
                #pragma unroll
                for (int mt = 0; mt < 2; mt++)
                    ldmx4(af[s][mt], abase + (u32)((aRow + (mt << 4)) * 144));
            }
            u32 bf[8][2];
            {
                const u32 bbase = stBase + (u32)2 * TILE_N + kb + bColB;
                #pragma unroll
                for (int p = 0; p < 4; p++) {
                    u32 t4[4];
                    ldmx4(t4, bbase + (u32)((bRow + (p << 4)) * 144));
                    bf[2*p][0] = t4[0]; bf[2*p][1] = t4[1];
                    bf[2*p+1][0] = t4[2]; bf[2*p+1][1] = t4[3];
                }
                #pragma unroll
                for (int s = 0; s < 2; s++)
                    #pragma unroll
                    for (int mt = 0; mt < 2; mt++)
                        #pragma unroll
                        for (int nt = 0; nt < 8; nt++)
                            mma16816(acc[mt][nt], af[s][mt], bf[nt]);
            }
            {
                const u32 bbase = stBase + (u32)3 * TILE_N + kb + bColB;
                #pragma unroll
                for (int p = 0; p < 4; p++) {
                    u32 t4[4];
                    ldmx4(t4, bbase + (u32)((bRow + (p << 4)) * 144));
                    bf[2*p][0] = t4[0]; bf[2*p][1] = t4[1];
                    bf[2*p+1][0] = t4[2]; bf[2*p+1][1] = t4[3];
                }
                #pragma unroll
                for (int mt = 0; mt < 2; mt++)
                    #pragma unroll
                    for (int nt = 0; nt < 8; nt++)
                        mma16816(acc[mt][nt], af[0][mt], bf[nt]);
            }
        }
        __syncthreads();
    }

    const int qr = lane >> 2;
    const int qc = (lane & 3) << 1;
    #pragma unroll
    for (int mt = 0; mt < 2; mt++) {
        #pragma unroll
        for (int half = 0; half < 2; half++) {
            const int r = rowBase + (warpM << 5) + (mt << 4) + (half << 3) + qr;
            #pragma unroll
            for (int nt = 0; nt < 8; nt++) {
                const int cc = colBase + (warpN << 6) + (nt << 3) + qc;
                float v0 = acc[mt][nt][2*half + 0];
                float v1 = acc[mt][nt][2*half + 1];
                if (bias) { v0 += __ldg(&bias[cc]); v1 += __ldg(&bias[cc + 1]); }
                if (epi == 1) {
                    v0 = 0.5f * v0 * (1.0f + erff(v0 * 0.7071067811865475f));
                    v1 = 0.5f * v1 * (1.0f + erff(v1 * 0.7071067811865475f));
                }
                if (resid) {
                    v0 += resid[(size_t)r * ldc + cc];
                    v1 += resid[(size_t)r * ldc + cc + 1];
                }
                *(float2*)(C + (size_t)r * ldc + cc) = make_float2(v0, v1);
            }
        }
    }
}

// ---------------- router self-attention -> bf16 split output ----------------
__global__ void __launch_bounds__(128) router_attn_kernel(
    const float* __restrict__ QKV, bf16* __restrict__ Os, size_t ss)
{
    __shared__ float sK[8 * 768];
    __shared__ float sV[8 * 768];
    const int t = blockIdx.x, tid = threadIdx.x;
    const float* base = QKV + (size_t)t * 8 * 2304;
    #pragma unroll
    for (int it = 0; it < 12; it++) {
        int i = tid + (it << 7);
        int pos = i / 192, c4 = i - pos * 192;
        ((float4*)sK)[i] = *(const float4*)(base + (size_t)pos * 2304 +  768 + c4 * 4);
        ((float4*)sV)[i] = *(const float4*)(base + (size_t)pos * 2304 + 1536 + c4 * 4);
    }
    __syncthreads();
    if (tid < 96) {
        const int head = tid / 8, qi = tid % 8;
        const float* q = base + (size_t)qi * 2304 + head * 64;
        float s[8] = {0.f};
        for (int d = 0; d < 64; d++) {
            float qd = q[d];
            #pragma unroll
            for (int m = 0; m < 8; m++) s[m] = fmaf(qd, sK[m * 768 + head * 64 + d], s[m]);
        }
        float mx = -1e30f;
        #pragma unroll
        for (int m = 0; m < 8; m++) { s[m] *= 0.125f; mx = fmaxf(mx, s[m]); }
        float den = 0.f;
        #pragma unroll
        for (int m = 0; m < 8; m++) { s[m] = expf(s[m] - mx); den += s[m]; }
        float inv = 1.0f / den;
        #pragma unroll
        for (int m = 0; m < 8; m++) s[m] *= inv;
        bf16* op = Os + (size_t)(t * 8 + qi) * 768 + head * 64;
        for (int d4 = 0; d4 < 16; d4++) {
            float4 o4;
            float* po = &o4.x;
            #pragma unroll
            for (int j = 0; j < 4; j++) {
                int d = d4 * 4 + j;
                float o = 0.f;
                #pragma unroll
                for (int m = 0; m < 8; m++) o = fmaf(s[m], sV[m * 768 + head * 64 + d], o);
                po[j] = o;
            }
            split4_store(o4, op + d4 * 4, op + ss + d4 * 4);
        }
    }
}

// ---------------- RMS-norm with residual; fp32 + optional split out ----------------
__global__ void __launch_bounds__(256) rms_kernel(
    const float* __restrict__ Y, const float* __restrict__ R,
    const float* __restrict__ W, float* __restrict__ O,
    bf16* __restrict__ Os, size_t oss)
{
    const int row = blockIdx.x, tid = threadIdx.x;
    float4 sv;
    float ssum = 0.f;
    if (tid < 192) {
        float4 vy = *(const float4*)(Y + (size_t)row * 768 + tid * 4);
        float4 vr = *(const float4*)(R + (size_t)row * 768 + tid * 4);
        sv.x = vy.x + vr.x; sv.y = vy.y + vr.y;
        sv.z = vy.z + vr.z; sv.w = vy.w + vr.w;
        ssum = sv.x*sv.x + sv.y*sv.y + sv.z*sv.z + sv.w*sv.w;
    }
    __shared__ float red[256];
    red[tid] = ssum; __syncthreads();
    for (int o = 128; o > 0; o >>= 1) { if (tid < o) red[tid] += red[tid + o]; __syncthreads(); }
    float scale = rsqrtf(red[0] * (1.0f / 768.0f) + 1e-5f);
    if (tid < 192) {
        float4 w = *(const float4*)(W + tid * 4);
        float4 o;
        o.x = sv.x * scale * w.x; o.y = sv.y * scale * w.y;
        o.z = sv.z * scale * w.z; o.w = sv.w * scale * w.w;
        size_t off = (size_t)row * 768 + tid * 4;
        *(float4*)(O + off) = o;
        if (Os) split4_store(o, Os + off, Os + oss + off);
    }
}

__global__ void __launch_bounds__(256) logits_kernel(
    const float* __restrict__ CTX, const float* __restrict__ GW,
    float* __restrict__ rprobs, int* __restrict__ tkidx,
    float* __restrict__ tkp, float* __restrict__ out_idx_f)
{
    const int t = blockIdx.x, tid = threadIdx.x;
    __shared__ float mv[768];
    const float* c0 = CTX + (size_t)t * 8 * 768;
    for (int i = tid; i < 768; i += 256) {
        float s = 0.f;
        #pragma unroll
        for (int p = 0; p < 8; p++) s += c0[p * 768 + i];
        mv[i] = s * 0.125f;
    }
    __syncthreads();
    const int w = tid >> 5, lane = tid & 31;
    float part = 0.f;
    for (int i = lane; i < 768; i += 32) part = fmaf(mv[i], GW[w * 768 + i], part);
    #pragma unroll
    for (int o = 16; o; o >>= 1) part += __shfl_xor_sync(0xffffffffu, part, o);
    __shared__ float lg[8];
    if (lane == 0) lg[w] = part;
    __syncthreads();
    if (tid == 0) {
        float mx = lg[0];
        #pragma unroll
        for (int e = 1; e < 8; e++) mx = fmaxf(mx, lg[e]);
        float ex[8], den = 0.f;
        #pragma unroll
        for (int e = 0; e < 8; e++) { ex[e] = expf(lg[e] - mx); den += ex[e]; }
        float inv = 1.0f / den;
        #pragma unroll
        for (int e = 0; e < 8; e++) rprobs[t * 8 + e] = ex[e] * inv;
        int i0 = 0;
        #pragma unroll
        for (int e = 1; e < 8; e++) if (lg[e] > lg[i0]) i0 = e;
        int i1 = -1;
        #pragma unroll
        for (int e = 0; e < 8; e++) if (e != i0 && (i1 < 0 || lg[e] > lg[i1])) i1 = e;
        tkidx[t * 2] = i0; tkidx[t * 2 + 1] = i1;
        float eb = expf(lg[i1] - lg[i0]);
        float p0 = 1.0f / (1.0f + eb);
        tkp[t * 2] = p0; tkp[t * 2 + 1] = eb * p0;
        if (out_idx_f) { out_idx_f[t * 2] = (float)i0; out_idx_f[t * 2 + 1] = (float)i1; }
    }
}

// ---------------- gather: fp32 + split output ----------------
__global__ void gather_kernel(const float* __restrict__ eo, const int* __restrict__ tkidx,
                              float* __restrict__ sf, bf16* __restrict__ sfS, size_t ss)
{
    const int total4 = TT * KX * DD / 4;
    for (int idx = blockIdx.x * blockDim.x + threadIdx.x; idx < total4; idx += gridDim.x * blockDim.x) {
        int d4 = idx % (DD / 4);
        int r = idx / (DD / 4);
        int t = r >> 1, k = r & 1;
        float4 v = *(const float4*)(eo + (size_t)t * EE * DD
                                    + (size_t)tkidx[t * 2 + k] * DD + d4 * 4);
        ((float4*)sf)[idx] = v;
        split4_store(v, sfS + 4 * (size_t)idx, sfS + ss + 4 * (size_t)idx);
    }
}

// ---------------- collab attention + entropy -> split output ----------------
__global__ void __launch_bounds__(256) collab_attn_kernel(
    const float* __restrict__ QKV, bf16* __restrict__ Os, size_t ss,
    float* __restrict__ ent)
{
    const int t = blockIdx.x, tid = threadIdx.x;
    const float* base = QKV + (size_t)t * 2 * 2304;
    __shared__ float sc[2][2][2];
    __shared__ float sp[2][2][2];
    const int w = tid >> 5, lane = tid & 31;
    {
        int h = (w >> 2) & 1, qi = (w >> 1) & 1, kj = w & 1;
        float part = 0.f;
        const float* qp = base + (size_t)qi * 2304 + h * 384;
        const float* kp = base + (size_t)kj * 2304 + 768 + h * 384;
        for (int d = lane; d < 384; d += 32) part = fmaf(qp[d], kp[d], part);
        #pragma unroll
        for (int o = 16; o; o >>= 1) part += __shfl_xor_sync(0xffffffffu, part, o);
        if (lane == 0) sc[h][qi][kj] = part * 0.05103103630798288f;
    }
    __syncthreads();
    if (tid < 4) {
        int h = tid >> 1, qi = tid & 1;
        float s0 = sc[h][qi][0], s1 = sc[h][qi][1];
        float m = fmaxf(s0, s1);
        float e0 = expf(s0 - m), e1 = expf(s1 - m);
        float inv = 1.0f / (e0 + e1);
        sp[h][qi][0] = e0 * inv; sp[h][qi][1] = e1 * inv;
    }
    __syncthreads();
    if (tid == 0) {
        float esum = 0.f;
        #pragma unroll
        for (int qi = 0; qi < 2; qi++) {
            float a0 = 0.5f * (sp[0][qi][0] + sp[1][qi][0]);
            float a1 = 0.5f * (sp[0][qi][1] + sp[1][qi][1]);
            esum -= a0 * logf(a0 + 1e-9f) + a1 * logf(a1 + 1e-9f);
        }
        ent[t] = esum;
    }
    for (int i4 = tid; i4 < 384; i4 += 256) {
        int qi = i4 / 192, c4 = i4 - qi * 192;
        int c = c4 * 4;
        int h = c / 384;
        float p0 = sp[h][qi][0], p1 = sp[h][qi][1];
        float4 v0 = *(const float4*)(base + 1536 + c);
        float4 v1 = *(const float4*)(base + 2304 + 1536 + c);
        float4 o;
        o.x = fmaf(p0, v0.x, p1 * v1.x); o.y = fmaf(p0, v0.y, p1 * v1.y);
        o.z = fmaf(p0, v0.z, p1 * v1.z); o.w = fmaf(p0, v0.w, p1 * v1.w);
        size_t off = (size_t)(t * 2 + qi) * 768 + c;
        split4_store(o, Os + off, Os + ss + off);
    }
}

// ---------------- weighted combine -> split output only ----------------
__global__ void combine_kernel(const float* __restrict__ ref, const float* __restrict__ tkp,
                               bf16* __restrict__ outS, size_t ss)
{
    const int total4 = TT * DD / 4;
    for (int idx = blockIdx.x * blockDim.x + threadIdx.x; idx < total4; idx += gridDim.x * blockDim.x) {
        int d4 = idx % (DD / 4);
        int t = idx / (DD / 4);
        float p0 = tkp[t * 2], p1 = tkp[t * 2 + 1];
        float4 a = *(const float4*)(ref + (size_t)(t * 2) * DD + d4 * 4);
        float4 b = *(const float4*)(ref + (size_t)(t * 2 + 1) * DD + d4 * 4);
        float4 o;
        o.x = fmaf(p0, a.x, p1 * b.x); o.y = fmaf(p0, a.y, p1 * b.y);
        o.z = fmaf(p0, a.z, p1 * b.z); o.w = fmaf(p0, a.w, p1 * b.w);
        split4_store(o, outS + 4 * (size_t)idx, outS + ss + 4 * (size_t)idx);
    }
}

__global__ void __launch_bounds__(256) aux_kernel(
    const float* __restrict__ rprobs, const float* __restrict__ ent, float* __restrict__ outp)
{
    const int tid = threadIdx.x;
    __shared__ float red[256];
    float us[8] = {0.f};
    for (int t = tid; t < TT; t += 256)
        #pragma unroll
        for (int e = 0; e < 8; e++) us[e] += rprobs[t * 8 + e];
    float usage[8];
    for (int e = 0; e < 8; e++) {
        red[tid] = us[e]; __syncthreads();
        for (int o = 128; o > 0; o >>= 1) { if (tid < o) red[tid] += red[tid + o]; __syncthreads(); }
        usage[e] = red[0] / (float)TT; __syncthreads();
    }
    float es = 0.f;
    for (int t = tid; t < TT; t += 256) es += ent[t];
    red[tid] = es; __syncthreads();
    for (int o = 128; o > 0; o >>= 1) { if (tid < o) red[tid] += red[tid + o]; __syncthreads(); }
    if (tid == 0) {
        float um = 0.f;
        #pragma unroll
        for (int e = 0; e < 8; e++) um += usage[e];
        um *= 0.125f;
        float bal = 0.f;
        #pragma unroll
        for (int e = 0; e < 8; e++) { float d = usage[e] - um; bal = fmaf(d, d, bal); }
        bal *= 0.125f;
        outp[0] = 0.1f * (0.01f * (red[0] / (float)(TT * KX)) + 0.01f * bal);
    }
}

// ---------------- host launch ----------------
extern "C" void kernel_launch(void* const* d_in, const int* in_sizes, int n_in,
                              void* d_out, int out_size)
{
    const float* x       = (const float*)d_in[0];
    const float* w1      = (const float*)d_in[1];
    const float* w3      = (const float*)d_in[2];
    const float* w2      = (const float*)d_in[3];
    const float* r_in_w  = (const float*)d_in[4];
    const float* r_in_b  = (const float*)d_in[5];
    const float* r_out_w = (const float*)d_in[6];
    const float* r_out_b = (const float*)d_in[7];
    const float* r_norm  = (const float*)d_in[8];
    const float* gate_w  = (const float*)d_in[9];
    const float* c_in_w  = (const float*)d_in[10];
    const float* c_in_b  = (const float*)d_in[11];
    const float* c_out_w = (const float*)d_in[12];
    const float* c_out_b = (const float*)d_in[13];
    const float* c_norm  = (const float*)d_in[14];
    const float* ffn_w1  = (const float*)d_in[15];
    const float* ffn_w2  = (const float*)d_in[16];
    const float* o_w     = (const float*)d_in[17];
    float* out = (float*)d_out;

    static cudaStream_t s2 = nullptr;
    static cudaEvent_t evFork = nullptr, evJoin = nullptr, evFork2 = nullptr, evJoin2 = nullptr;
    static bool attr_done = false;
    if (!attr_done) {
        cudaFuncSetAttribute(tgemmW, cudaFuncAttributeMaxDynamicSharedMemorySize, SMEM_W);
        cudaFuncSetAttribute(tgemmN, cudaFuncAttributeMaxDynamicSharedMemorySize, SMEM_N);
        cudaStreamCreateWithFlags(&s2, cudaStreamNonBlocking);
        cudaEventCreateWithFlags(&evFork,  cudaEventDisableTiming);
        cudaEventCreateWithFlags(&evJoin,  cudaEventDisableTiming);
        cudaEventCreateWithFlags(&evFork2, cudaEventDisableTiming);
        cudaEventCreateWithFlags(&evJoin2, cudaEventDisableTiming);
        attr_done = true;
    }

    float *gateup, *eo, *qkv, *proj, *ctx, *rprobs, *tkp, *sf, *ao, *h1, *ref, *ent;
    int* tkidx;
    bf16 *xS, *w13T, *w2T, *actS, *eoS, *gS, *rinS, *routS, *cinS, *coutS, *f1S, *f2S, *owS;
    cudaGetSymbolAddress((void**)&gateup, g_gateup);
    cudaGetSymbolAddress((void**)&eo,    g_eo);
    cudaGetSymbolAddress((void**)&qkv,   g_qkv);
    cudaGetSymbolAddress((void**)&proj,  g_proj);
    cudaGetSymbolAddress((void**)&ctx,   g_ctx);
    cudaGetSymbolAddress((void**)&rprobs,g_rprobs);
    cudaGetSymbolAddress((void**)&tkidx, g_tkidx);
    cudaGetSymbolAddress((void**)&tkp,   g_tkp);
    cudaGetSymbolAddress((void**)&sf,    g_sf);
    cudaGetSymbolAddress((void**)&ao,    g_ao);
    cudaGetSymbolAddress((void**)&h1,    g_h1);
    cudaGetSymbolAddress((void**)&ref,   g_ref);
    cudaGetSymbolAddress((void**)&ent,   g_ent);
    cudaGetSymbolAddress((void**)&xS,    g_xS);
    cudaGetSymbolAddress((void**)&w13T,  g_w13T);
    cudaGetSymbolAddress((void**)&w2T,   g_w2T);
    cudaGetSymbolAddress((void**)&actS,  g_actS);
    cudaGetSymbolAddress((void**)&eoS,   g_eoS);
    cudaGetSymbolAddress((void**)&gS,    g_gS);
    cudaGetSymbolAddress((void**)&rinS,  g_rinS);
    cudaGetSymbolAddress((void**)&routS, g_routS);
    cudaGetSymbolAddress((void**)&cinS,  g_cinS);
    cudaGetSymbolAddress((void**)&coutS, g_coutS);
    cudaGetSymbolAddress((void**)&f1S,   g_f1S);
    cudaGetSymbolAddress((void**)&f2S,   g_f2S);
    cudaGetSymbolAddress((void**)&owS,   g_owS);

    const bool write_idx = out_size >= (TT * DD + 1 + TT * KX);
    const bool write_aux = out_size >= (TT * DD + 1);
    const size_t sEHD = (size_t)EE * HH * DD;
    const size_t sETH = (size_t)EE * TT * HH;
    const size_t sBig = (size_t)TT * EE * DD;
    const size_t sMid = (size_t)TT * KX * DD;
    const size_t sSm  = (size_t)TT * DD;
    dim3 tb32(32, 8);

    // ---- fork: side stream weight prep concurrent with gate+up path ----
    cudaEventRecord(evFork, 0);
    cudaStreamWaitEvent(s2, evFork, 0);
    tsplit<<<dim3(DD/32, HH/32, EE), tb32, 0, s2>>>(w2, w2T, HH, DD, (size_t)EE * DD * HH);
    split3<<<512, 256, 0, s2>>>(r_in_w, rinS, (size_t)3*DD*DD, (size_t)3*DD*DD/4);
    split3<<<256, 256, 0, s2>>>(r_out_w, routS, (size_t)DD*DD, (size_t)DD*DD/4);
    split3<<<512, 256, 0, s2>>>(c_in_w, cinS, (size_t)3*DD*DD, (size_t)3*DD*DD/4);
    split3<<<256, 256, 0, s2>>>(c_out_w, coutS, (size_t)DD*DD, (size_t)DD*DD/4);
    split3<<<256, 256, 0, s2>>>(ffn_w1, f1S, (size_t)DD*DD, (size_t)DD*DD/4);
    split3<<<256, 256, 0, s2>>>(ffn_w2, f2S, (size_t)DD*DD, (size_t)DD*DD/4);
    split3<<<256, 256, 0, s2>>>(o_w, owS, (size_t)DD*DD, (size_t)DD*DD/4);
    cudaEventRecord(evJoin, s2);

    // main stream
    split3<<<512, 256>>>(x, xS, sSm, sSm / 4);
    tsplit<<<dim3(HH/32, DD/32, EE), tb32>>>(w1, w13T, DD, HH, 2*sEHD);
    tsplit<<<dim3(HH/32, DD/32, EE), tb32>>>(w3, w13T + sEHD, DD, HH, 2*sEHD);
    tgemmW<<<dim3(HH/256, TT/128, 16), 512, SMEM_W>>>(
        xS, sSm, 0, w13T, 2*sEHD, (size_t)HH*DD, DD,
        nullptr, nullptr, gateup, HH, (size_t)TT*HH, 0);
    split3_swiglu<<<4096, 256>>>(gateup, gateup + sETH, actS, sETH, sETH / 4);

    cudaStreamWaitEvent(0, evJoin, 0);

    // expert down-proj (tgemmN: 1536 CTAs -> better wave quantization than 768)
    tgemmN<<<dim3(DD/128, TT/128, EE), 256, SMEM_N>>>(
        actS, sETH, (size_t)TT*HH, w2T, (size_t)EE*DD*HH, (size_t)DD*HH, HH,
        nullptr, nullptr, eo, EE*DD, (size_t)DD, 0);
    // router qkv
    split3<<<2048, 256>>>(eo, eoS, sBig, sBig / 4);
    tgemmW<<<dim3(3*DD/256, TT*EE/128, 1), 512, SMEM_W>>>(
        eoS, sBig, 0, rinS, (size_t)3*DD*DD, 0, DD,
        r_in_b, nullptr, qkv, 3*DD, 0, 0);
    // router attention -> gS splits (fused)
    router_attn_kernel<<<TT, 128>>>(qkv, gS, sBig);
    // router out-proj (tgemmN: 1536 CTAs)
    tgemmN<<<dim3(DD/128, TT*EE/128, 1), 256, SMEM_N>>>(
        gS, sBig, 0, routS, (size_t)DD*DD, 0, DD,
        r_out_b, nullptr, proj, DD, 0, 0);
    // residual + RMS -> ctx fp32
    rms_kernel<<<TT * EE, 256>>>(proj, eo, r_norm, ctx, nullptr, 0);
    // logits / top-2
    logits_kernel<<<TT, 256>>>(ctx, gate_w, rprobs, tkidx, tkp,
                               write_idx ? out + sSm + 1 : nullptr);
    // gather -> sf fp32 + gS splits (fused)
    gather_kernel<<<1024, 256>>>(eo, tkidx, sf, gS, sMid);
    // collab qkv
    tgemmN<<<dim3(3*DD/128, TT*KX/128, 1), 256, SMEM_N>>>(
        gS, sMid, 0, cinS, (size_t)3*DD*DD, 0, DD,
        c_in_b, nullptr, qkv, 3*DD, 0, 0);
    // collab attention + entropy -> gS splits (fused)
    collab_attn_kernel<<<TT, 256>>>(qkv, gS, sMid, ent);

    // ---- fork 2: aux loss on side stream ----
    if (write_aux) {
        cudaEventRecord(evFork2, 0);
        cudaStreamWaitEvent(s2, evFork2, 0);
        aux_kernel<<<1, 256, 0, s2>>>(rprobs, ent, out + sSm);
        cudaEventRecord(evJoin2, s2);
    }

    // collab out-proj
    tgemmN<<<dim3(DD/128, TT*KX/128, 1), 256, SMEM_N>>>(
        gS, sMid, 0, coutS, (size_t)DD*DD, 0, DD,
        c_out_b, nullptr, proj, DD, 0, 0);
    // residual + RMS -> ao fp32 + gS splits (fused)
    rms_kernel<<<TT * KX, 256>>>(proj, sf, c_norm, ao, gS, sMid);
    // FFN up + GELU
    tgemmN<<<dim3(DD/128, TT*KX/128, 1), 256, SMEM_N>>>(
        gS, sMid, 0, f1S, (size_t)DD*DD, 0, DD,
        nullptr, nullptr, h1, DD, 0, 1);
    // FFN down + residual(ao)
    split3<<<1024, 256>>>(h1, gS, sMid, sMid / 4);
    tgemmN<<<dim3(DD/128, TT*KX/128, 1), 256, SMEM_N>>>(
        gS, sMid, 0, f2S, (size_t)DD*DD, 0, DD,
        nullptr, ao, ref, DD, 0, 0);
    // combine -> gS splits (fused)
    combine_kernel<<<1024, 256>>>(ref, tkp, gS, sSm);
    // output projection
    tgemmN<<<dim3(DD/128, TT/128, 1), 256, SMEM_N>>>(
        gS, sSm, 0, owS, (size_t)DD*DD, 0, DD,
        nullptr, nullptr, out, DD, 0, 0);

    if (write_aux)
        cudaStreamWaitEvent(0, evJoin2, 0);
}